// round 9
// baseline (speedup 1.0000x reference)
#include <cuda_runtime.h>

#define NN 8
#define CC 64
#define HH 128
#define WW 128
#define TAPS 9
#define STEPS 10
#define EPSV 1e-5f
#define WPAD 12      // packed weights per pixel (9 taps + pad), 48B

// Scratch (__device__ globals -- no allocation allowed in kernel_launch)
__device__ float g_wp[(size_t)NN * HH * WW * WPAD];  // packed norm. weights, 6.3MB
__device__ float g_a[(size_t)NN * HH * WW * CC];     // NHWC ping, 33.5MB
__device__ float g_b[(size_t)NN * HH * WW * CC];     // NHWC pong, 33.5MB

// ---------------------------------------------------------------------------
// Normalize + pack: g_wp[n,h,w,0..8] = w[n,t,h,w] / (sum_t + eps), [9..11]=0
// ---------------------------------------------------------------------------
__global__ void mp_normpack_kernel(const float* __restrict__ wt) {
    int idx = blockIdx.x * blockDim.x + threadIdx.x;   // over N*H*W = 131072
    if (idx >= NN * HH * WW) return;
    int hw = idx % (HH * WW);
    int n  = idx / (HH * WW);
    const float* base = wt + (size_t)n * TAPS * HH * WW + hw;
    float v[TAPS];
    float s = EPSV;
#pragma unroll
    for (int t = 0; t < TAPS; t++) {
        v[t] = base[(size_t)t * HH * WW];
        s += v[t];
    }
    float inv = 1.0f / s;
    float* o = g_wp + (size_t)idx * WPAD;   // 48B-aligned
    *(float4*)(o + 0) = make_float4(v[0]*inv, v[1]*inv, v[2]*inv, v[3]*inv);
    *(float4*)(o + 4) = make_float4(v[4]*inv, v[5]*inv, v[6]*inv, v[7]*inv);
    *(float4*)(o + 8) = make_float4(v[8]*inv, 0.f, 0.f, 0.f);
}

// ---------------------------------------------------------------------------
// Transpose in: [n,c,hw] -> NHWC [n,hw,c], 32x32 smem tiles, coalesced both sides
// ---------------------------------------------------------------------------
__global__ void t_in_kernel(const float* __restrict__ src) {
    __shared__ float tile[32][33];
    int b   = blockIdx.x;                 // 512 hwT * 2 cT * 8 n = 8192
    int hwt = b & 511;  b >>= 9;
    int ct  = b & 1;    b >>= 1;
    int n   = b;
    int tx = threadIdx.x & 31, ty = threadIdx.x >> 5;   // 32x8
    int hw0 = hwt * 32, c0 = ct * 32;
    const float* in  = src + (size_t)n * CC * HH * WW;
    float*       out = g_a + (size_t)n * HH * WW * CC;
#pragma unroll
    for (int i = ty; i < 32; i += 8)
        tile[i][tx] = in[(size_t)(c0 + i) * (HH * WW) + hw0 + tx];
    __syncthreads();
#pragma unroll
    for (int i = ty; i < 32; i += 8)
        out[(size_t)(hw0 + i) * CC + c0 + tx] = tile[tx][i];
}

// ---------------------------------------------------------------------------
// Transpose out: NHWC [n,hw,c] -> NCHW [n,c,hw] into d_out
// ---------------------------------------------------------------------------
__global__ void t_out_kernel(const float* __restrict__ src, float* __restrict__ dst) {
    __shared__ float tile[32][33];
    int b   = blockIdx.x;
    int hwt = b & 511;  b >>= 9;
    int ct  = b & 1;    b >>= 1;
    int n   = b;
    int tx = threadIdx.x & 31, ty = threadIdx.x >> 5;
    int hw0 = hwt * 32, c0 = ct * 32;
    const float* in  = src + (size_t)n * HH * WW * CC;
    float*       out = dst + (size_t)n * CC * HH * WW;
#pragma unroll
    for (int i = ty; i < 32; i += 8)
        tile[i][tx] = in[(size_t)(hw0 + i) * CC + c0 + tx];
    __syncthreads();
#pragma unroll
    for (int i = ty; i < 32; i += 8)
        out[(size_t)(c0 + i) * (HH * WW) + hw0 + tx] = tile[tx][i];
}

// ---------------------------------------------------------------------------
// One step in NHWC. Warp = (n, h, 32-px w-segment); lane = channel pair
// (float2, 64 ch across 32 lanes). Sliding 3x3 column window along w:
//   per pixel: 3 coalesced 256B x-loads (new column), 3 warp-uniform
//   weight loads (1 bcast sector each), 18 FMA, 1 256B store.
// NO shuffles, NO barriers; h-border branches are warp-uniform.
// ---------------------------------------------------------------------------
#define WSEG 32

__global__ void __launch_bounds__(256, 4) mp_step_nhwc(
    const float* __restrict__ xin, float* __restrict__ xout)
{
    int gw   = blockIdx.x * 8 + (threadIdx.x >> 5);   // 0..4095
    int lane = threadIdx.x & 31;
    const int seg = gw & 3;   gw >>= 2;
    const int h   = gw & 127; gw >>= 7;
    const int n   = gw;
    const int w0  = seg * WSEG;

    const size_t rs = (size_t)WW * CC;                // row stride = 8192
    const float* r1 = xin + ((size_t)n * HH + h) * rs + 2 * lane;
    const float* r0 = r1 - rs;
    const float* r2 = r1 + rs;
    float*       ob = xout + ((size_t)n * HH + h) * rs + 2 * lane;
    const float* wp = g_wp + (((size_t)n * HH + h) * WW + w0) * WPAD;

    const bool up = (h > 0), dn = (h + 1 < HH);
    const float2 Z = make_float2(0.f, 0.f);

    float2 L0, L1, L2, C0, C1, C2, R0, R1, R2;
    // init window: column w0-1 (L) and w0 (C)
    if (w0 > 0) {
        L0 = up ? *(const float2*)(r0 + (size_t)(w0 - 1) * CC) : Z;
        L1 =      *(const float2*)(r1 + (size_t)(w0 - 1) * CC);
        L2 = dn ? *(const float2*)(r2 + (size_t)(w0 - 1) * CC) : Z;
    } else { L0 = L1 = L2 = Z; }
    C0 = up ? *(const float2*)(r0 + (size_t)w0 * CC) : Z;
    C1 =      *(const float2*)(r1 + (size_t)w0 * CC);
    C2 = dn ? *(const float2*)(r2 + (size_t)w0 * CC) : Z;

#pragma unroll 4
    for (int j = 0; j < WSEG; j++) {
        const int w = w0 + j;
        if (w + 1 < WW) {
            R0 = up ? *(const float2*)(r0 + (size_t)(w + 1) * CC) : Z;
            R1 =      *(const float2*)(r1 + (size_t)(w + 1) * CC);
            R2 = dn ? *(const float2*)(r2 + (size_t)(w + 1) * CC) : Z;
        } else { R0 = R1 = R2 = Z; }

        const float4 u0 = *(const float4*)(wp + j * WPAD);      // taps 0..3
        const float4 u1 = *(const float4*)(wp + j * WPAD + 4);  // taps 4..7
        const float  u2 = *(const float*) (wp + j * WPAD + 8);  // tap 8

        float2 acc;
        acc.x = u0.x * L0.x + u0.y * C0.x + u0.z * R0.x
              + u0.w * L1.x + u1.x * C1.x + u1.y * R1.x
              + u1.z * L2.x + u1.w * C2.x + u2  * R2.x;
        acc.y = u0.x * L0.y + u0.y * C0.y + u0.z * R0.y
              + u0.w * L1.y + u1.x * C1.y + u1.y * R1.y
              + u1.z * L2.y + u1.w * C2.y + u2  * R2.y;
        *(float2*)(ob + (size_t)w * CC) = acc;

        L0 = C0; L1 = C1; L2 = C2;
        C0 = R0; C1 = R1; C2 = R2;
    }
}

// ---------------------------------------------------------------------------
// kernel_launch: normalize+pack, NHWC-transpose in, 10 ping-pong NHWC steps
// (ends in g_a), transpose out to d_out.
// ---------------------------------------------------------------------------
extern "C" void kernel_launch(void* const* d_in, const int* in_sizes, int n_in,
                              void* d_out, int out_size) {
    (void)in_sizes; (void)n_in; (void)out_size;
    const float* input  = (const float*)d_in[0];
    const float* weight = (const float*)d_in[1];
    float* out = (float*)d_out;

    float *pa = nullptr, *pb = nullptr;
    cudaGetSymbolAddress((void**)&pa, g_a);
    cudaGetSymbolAddress((void**)&pb, g_b);

    mp_normpack_kernel<<<(NN * HH * WW + 255) / 256, 256>>>(weight);
    t_in_kernel<<<8192, 256>>>(input);          // input -> g_a (NHWC)

    const int stepBlocks = (NN * HH * (WW / WSEG) * 32) / 256;  // 512
    const float* src = pa;
    float* dst = pb;
    for (int k = 0; k < STEPS; k++) {
        mp_step_nhwc<<<stepBlocks, 256>>>(src, dst);
        const float* t = dst; dst = (float*)src; src = t;
    }
    // STEPS=10 even -> final result back in g_a
    t_out_kernel<<<8192, 256>>>(pa, out);
}

// round 10
// speedup vs baseline: 1.0885x; 1.0885x over previous
#include <cuda_runtime.h>
#include <cstdint>

#define NN 8
#define CC 64
#define HH 128
#define WW 128
#define TAPS 9
#define STEPS 10
#define EPSV 1e-5f

// Scratch: normalized weights [n,9,h,w] and ping-pong x buffer [n,c,h,w]
__device__ float g_nw[(size_t)NN * TAPS * HH * WW];
__device__ float g_x[(size_t)NN * CC * HH * WW];

// ---------------------------------------------------------------------------
// Normalize: nw[n,t,h,w] = w[n,t,h,w] / (sum_t w + eps)
// ---------------------------------------------------------------------------
__global__ void mp_normalize_kernel(const float* __restrict__ wt) {
    int idx = blockIdx.x * blockDim.x + threadIdx.x;   // over N*H*W
    if (idx >= NN * HH * WW) return;
    int hw = idx % (HH * WW);
    int n  = idx / (HH * WW);
    const float* base = wt + (size_t)n * TAPS * HH * WW + hw;
    float v[TAPS];
    float s = EPSV;
#pragma unroll
    for (int t = 0; t < TAPS; t++) {
        v[t] = base[(size_t)t * HH * WW];
        s += v[t];
    }
    float inv = 1.0f / s;
    float* out = g_nw + (size_t)n * TAPS * HH * WW + hw;
#pragma unroll
    for (int t = 0; t < TAPS; t++)
        out[(size_t)t * HH * WW] = v[t] * inv;
}

// ---------------------------------------------------------------------------
// cp.async helpers
// ---------------------------------------------------------------------------
__device__ __forceinline__ void cp_async16(uint32_t dst, const float* src, int nbytes) {
    asm volatile("cp.async.cg.shared.global [%0], [%1], 16, %2;\n"
                 :: "r"(dst), "l"(src), "r"(nbytes));
}
__device__ __forceinline__ void cp_commit() {
    asm volatile("cp.async.commit_group;\n" ::: "memory");
}
__device__ __forceinline__ void cp_wait2() {
    asm volatile("cp.async.wait_group 2;\n" ::: "memory");
}

// ---------------------------------------------------------------------------
// One step, per-warp cp.async pipeline (round-5 geometry, zero block syncs).
// Warp = (n, cb, h): lanes cover the full 128-px row (4 px/lane), 8 channels.
// 3-stage smem ring per warp: while computing channel c from smem, channel
// c+2's three x-rows are in flight via LDGSTS (L2 latency hidden by ~2
// channel-iterations of compute). Halo rows zero-fill via src-size=0; w-halo
// read directly from smem (shuffles eliminated). Weights: 36 regs, as before.
// ---------------------------------------------------------------------------
#define SW 4
#define CBLKS 8
#define CPB (CC / CBLKS)   // 8
#define NSTG 3

__global__ void __launch_bounds__(256, 4) mp_step_pipe(
    const float* __restrict__ xin, float* __restrict__ xout)
{
    __shared__ float buf[8][NSTG][3][WW];    // 8 warps x 3 stages x 3 rows = 36 KB

    const int wid  = threadIdx.x >> 5;
    const int lane = threadIdx.x & 31;
    const int w0   = lane * SW;

    int gw = blockIdx.x * 8 + wid;           // 8192 warps total
    const int h  = gw & (HH - 1);  gw >>= 7;
    const int n  = gw & (NN - 1);
    const int cb = gw >> 3;

    // Per-thread weights: 9 taps x 4 px = 36 regs, reused over 8 channels
    float wv[TAPS][SW];
#pragma unroll
    for (int t = 0; t < TAPS; t++) {
        float4 a = *(const float4*)(g_nw + (((size_t)n * TAPS + t) * HH + h) * WW + w0);
        wv[t][0] = a.x; wv[t][1] = a.y; wv[t][2] = a.z; wv[t][3] = a.w;
    }

    const size_t plane = (size_t)HH * WW;
    const float* xb = xin  + ((size_t)n * CC + cb * CPB) * plane;
    float*       ob = xout + ((size_t)n * CC + cb * CPB) * plane + (size_t)h * WW + w0;

    // Row validity / clamped source rows (addresses always in-bounds;
    // src-size=0 performs the zero-fill for out-of-image rows).
    int rowOK[3], rowG[3];
#pragma unroll
    for (int r = 0; r < 3; r++) {
        int g = h - 1 + r;
        rowOK[r] = (g >= 0 && g < HH) ? 16 : 0;
        rowG[r]  = g < 0 ? 0 : (g >= HH ? HH - 1 : g);
    }

    uint32_t sbase[NSTG][3];
#pragma unroll
    for (int st = 0; st < NSTG; st++)
#pragma unroll
        for (int r = 0; r < 3; r++)
            sbase[st][r] = (uint32_t)__cvta_generic_to_shared(&buf[wid][st][r][w0]);

    // Prologue: prefetch channels 0 and 1
#pragma unroll
    for (int c0 = 0; c0 < 2; c0++) {
        const float* base = xb + (size_t)c0 * plane;
#pragma unroll
        for (int r = 0; r < 3; r++)
            cp_async16(sbase[c0][r], base + (size_t)rowG[r] * WW + w0, rowOK[r]);
        cp_commit();
    }

#pragma unroll
    for (int c = 0; c < CPB; c++) {
        // Prefetch channel c+2 (or empty commit to keep group count uniform)
        if (c + 2 < CPB) {
            const float* base = xb + (size_t)(c + 2) * plane;
            const int st = (c + 2) % NSTG;
#pragma unroll
            for (int r = 0; r < 3; r++)
                cp_async16(sbase[st][r], base + (size_t)rowG[r] * WW + w0, rowOK[r]);
        }
        cp_commit();
        cp_wait2();          // group for channel c complete (<=2 newer pending)
        __syncwarp();        // cross-lane visibility of prefetched rows

        const float (*T)[WW] = buf[wid][c % NSTG];
        float acc0 = 0.f, acc1 = 0.f, acc2 = 0.f, acc3 = 0.f;
#pragma unroll
        for (int r = 0; r < 3; r++) {
            float4 A = *(const float4*)&T[r][w0];
            int li = w0 - 1; if (li < 0) li = 0;           // safe addr
            int ri = w0 + 4; if (ri > WW - 1) ri = WW - 1;
            float vl = T[r][li]; vl = (lane == 0)  ? 0.f : vl;
            float vr = T[r][ri]; vr = (lane == 31) ? 0.f : vr;

            const float* wL = wv[r * 3 + 0];
            const float* wC = wv[r * 3 + 1];
            const float* wR = wv[r * 3 + 2];
            acc0 += wL[0] * vl  + wC[0] * A.x + wR[0] * A.y;
            acc1 += wL[1] * A.x + wC[1] * A.y + wR[1] * A.z;
            acc2 += wL[2] * A.y + wC[2] * A.z + wR[2] * A.w;
            acc3 += wL[3] * A.z + wC[3] * A.w + wR[3] * vr;
        }
        *(float4*)(ob + (size_t)c * plane) = make_float4(acc0, acc1, acc2, acc3);
        __syncwarp();        // all lanes done reading stage before its reuse
    }
}

// ---------------------------------------------------------------------------
// kernel_launch: normalize once, then 10 ping-pong steps ending in d_out.
// ---------------------------------------------------------------------------
extern "C" void kernel_launch(void* const* d_in, const int* in_sizes, int n_in,
                              void* d_out, int out_size) {
    (void)in_sizes; (void)n_in; (void)out_size;
    const float* input  = (const float*)d_in[0];
    const float* weight = (const float*)d_in[1];
    float* out = (float*)d_out;

    float* xscr = nullptr;
    cudaGetSymbolAddress((void**)&xscr, g_x);

    const int threads = 256;
    {
        int total = NN * HH * WW;
        mp_normalize_kernel<<<(total + threads - 1) / threads, threads>>>(weight);
    }

    const int blocks = CBLKS * NN * HH / 8;   // 8192 warps / 8 per block = 1024

    // 10 hops: in -> g_x -> out -> g_x -> out ... (step 10 ends in d_out)
    const float* src = input;
    for (int k = 1; k <= STEPS; k++) {
        float* dst = (k & 1) ? xscr : out;
        mp_step_pipe<<<blocks, threads>>>(src, dst);
        src = dst;
    }
}